// round 17
// baseline (speedup 1.0000x reference)
#include <cuda_runtime.h>
#include <cuda_bf16.h>
#include <math.h>
#include <stdint.h>

#define Bb  64
#define Tt  48
#define Hh  512
#define Ee  512
#define ATT 196
#define AF  2048
#define FCD 2048
#define Vv  10000
#define VPAD 10112
#define NBLK 148

// ---------------- device scratch (no allocs allowed) ----------------
__device__ __align__(16) float g_h[Bb*Tt*Hh];
__device__ __align__(16) float g_c[Bb*Tt*Hh];
__device__ __align__(16) float g_fcp[8][Bb*Ee];
__device__ __align__(16) float g_patt[Bb*ATT*Ee];
__device__ __align__(16) float g_pI[Bb*ATT*Hh];
__device__ __align__(16) float g_Wq[Ee*1024];
__device__ __align__(16) float g_bq[Ee];
__device__ __align__(16) float g_catX[Bb*2048];
__device__ __align__(16) float g_catF1[Bb*1024];
__device__ __align__(16) float g_catF2[Bb*1024];
__device__ __align__(16) float g_hcat[Bb*1024];
__device__ __align__(16) float g_qp[8][Bb*Hh];
__device__ __align__(16) float g_gatesP[16][Bb*1024];
__device__ __align__(16) float g_cg0P[16][Bb*Hh];
__device__ __align__(16) float g_cgatt[Bb*Hh];
__device__ __align__(16) float g_f1P[8][Bb*Hh];
__device__ __align__(16) float g_f2P[8][Bb*Hh];
__device__ __align__(16) float g_ca[Bb*Hh];
__device__ __align__(16) float g_cf[Bb*Hh];

// packed bf16 hi/lo operands
__device__ __align__(16) unsigned cAFH[Bb*ATT*1024], cAFL[Bb*ATT*1024];
__device__ __align__(16) unsigned cWATH[Ee*1024],  cWATL[Ee*1024];
__device__ __align__(16) unsigned cWIATH[Hh*1024], cWIATL[Hh*1024];
__device__ __align__(16) unsigned cWLH[VPAD*256],  cWLL[VPAD*256];
__device__ __align__(16) unsigned cWHH[1024*1024], cWHL[1024*1024];
__device__ __align__(16) unsigned cWIH[Hh*1024],   cWIL[Hh*1024];
__device__ __align__(16) unsigned cWF1H[Hh*512],   cWF1L[Hh*512];
__device__ __align__(16) unsigned cWF2H[Hh*512],   cWF2L[Hh*512];
__device__ __align__(16) unsigned cWQH[Hh*512],    cWQL[Hh*512];

// software grid barrier state
__device__ int g_barc = 0;
__device__ volatile int g_barg = 0;

__device__ __forceinline__ void grid_sync_() {
    __syncthreads();
    if (threadIdx.x == 0) {
        int gen = g_barg;
        __threadfence();
        int t = atomicAdd(&g_barc, 1);
        if (t == (int)gridDim.x - 1) {
            g_barc = 0;
            __threadfence();
            g_barg = gen + 1;
        } else {
            while (g_barg == gen) { }
        }
        __threadfence();
    }
    __syncthreads();
}

__device__ __forceinline__ float tanh_approx(float x) {
    float y;
    asm("tanh.approx.f32 %0, %1;" : "=f"(y) : "f"(x));
    return y;
}

__device__ __forceinline__ void cvt2(float f0, float f1, unsigned &h, unsigned &l) {
    __nv_bfloat162 hb = __floats2bfloat162_rn(f0, f1);
    float g0 = __bfloat162float(hb.x), g1 = __bfloat162float(hb.y);
    __nv_bfloat162 lb = __floats2bfloat162_rn(f0 - g0, f1 - g1);
    h = *reinterpret_cast<unsigned*>(&hb);
    l = *reinterpret_cast<unsigned*>(&lb);
}

__device__ __forceinline__ void mma_bf16(float* d, const unsigned* a, unsigned b0, unsigned b1) {
    asm volatile("mma.sync.aligned.m16n8k16.row.col.f32.bf16.bf16.f32 "
        "{%0,%1,%2,%3}, {%4,%5,%6,%7}, {%8,%9}, {%0,%1,%2,%3};"
        : "+f"(d[0]), "+f"(d[1]), "+f"(d[2]), "+f"(d[3])
        : "r"(a[0]), "r"(a[1]), "r"(a[2]), "r"(a[3]), "r"(b0), "r"(b1));
}

// ---------------- init kernels ----------------
__global__ void k_zero_hc() {
    int idx = blockIdx.x * blockDim.x + threadIdx.x;
    int n = Bb*Tt*Hh;
    for (int i = idx; i < n; i += gridDim.x * blockDim.x) { g_h[i] = 0.f; g_c[i] = 0.f; }
}

__global__ void k_build_wq(const float* __restrict__ W_ha, const float* __restrict__ b_ha,
                           const float* __restrict__ W_hf, const float* __restrict__ b_hf) {
    int n = blockIdx.x;
    for (int k = threadIdx.x; k < Hh; k += blockDim.x) {
        g_Wq[n*1024 + k]      = W_ha[n*Hh + k];
        g_Wq[n*1024 + Hh + k] = W_hf[n*Hh + k];
    }
    if (threadIdx.x == 0) g_bq[n] = b_ha[n] + b_hf[n];
}

__global__ void k_cvt(int which, const float* __restrict__ src, int ld, int R, int C, int Rpad) {
    unsigned *dH, *dL;
    switch (which) {
        case 0: dH = cAFH;  dL = cAFL;  break;
        case 1: dH = cWATH; dL = cWATL; break;
        case 2: dH = cWIATH;dL = cWIATL;break;
        case 3: dH = cWLH;  dL = cWLL;  break;
        case 4: dH = cWHH;  dL = cWHL;  break;
        case 5: dH = cWIH;  dL = cWIL;  break;
        case 6: dH = cWF1H; dL = cWF1L; break;
        case 7: dH = cWF2H; dL = cWF2L; break;
        default: dH = cWQH; dL = cWQL; src = g_Wq; break;
    }
    int C2 = C >> 1;
    long total = (long)Rpad * C2;
    long stride = (long)gridDim.x * blockDim.x;
    for (long idx = (long)blockIdx.x*blockDim.x + threadIdx.x; idx < total; idx += stride) {
        int r = (int)(idx / C2), cp = (int)(idx % C2);
        float f0 = 0.f, f1 = 0.f;
        if (r < R) {
            const float* p = src + (size_t)r*ld + 2*cp;
            f0 = p[0]; f1 = p[1];
        }
        unsigned h, l;
        cvt2(f0, f1, h, l);
        dH[idx] = h; dL[idx] = l;
    }
}

__global__ void k_pmean() {
    int b = blockIdx.x;
    int d = blockIdx.y * 128 + threadIdx.x;
    const float* p = g_pI + ((size_t)b*ATT)*Hh + d;
    float acc = 0.f;
#pragma unroll 4
    for (int a = 0; a < ATT; a++) acc += p[(size_t)a*Hh];
    g_cgatt[b*Hh + d] = acc * (1.0f/ATT);
}

// ---------------- big GEMM (bf16x3 tensor) ----------------
__global__ void __launch_bounds__(256, 2)
k_gemm_bigbf(int mode, const float* __restrict__ bias, float* __restrict__ Cext,
             int M, int N, int K) {
    const unsigned *AH = nullptr, *AL = nullptr, *WHp, *WLp;
    float* C;
    if (mode == 0)      { AH = cAFH; AL = cAFL; WHp = cWATH;  WLp = cWATL;  C = g_patt; }
    else if (mode == 2) { AH = cAFH; AL = cAFL; WHp = cWIATH; WLp = cWIATL; C = g_pI; }
    else                { WHp = cWLH; WLp = cWLL; C = Cext; }
    int K2 = K >> 1;

    __shared__ unsigned sAH[128][20], sAL[128][20], sWH[128][20], sWL[128][20];

    int tid = threadIdx.x;
    int m0 = blockIdx.y * 128, n0 = blockIdx.x * 128;
    int warp = tid >> 5, lane = tid & 31;
    int grp = lane >> 2, qd = lane & 3;
    int wm = (warp & 3) * 32;
    int wn = (warp >> 2) * 64;
    int sr = tid >> 1, sc = (tid & 1) * 8;

    float acc[2][8][4];
#pragma unroll
    for (int mi = 0; mi < 2; mi++)
#pragma unroll
        for (int ni = 0; ni < 8; ni++)
#pragma unroll
            for (int r = 0; r < 4; r++) acc[mi][ni][r] = 0.f;

    for (int k0 = 0; k0 < K2; k0 += 16) {
        uint4 va0, va1, vb0, vb1;
        unsigned hh[8], ll[8];
        if (mode != 1) {
            const unsigned* ah = &AH[(size_t)(m0 + sr)*K2 + k0 + sc];
            const unsigned* al = &AL[(size_t)(m0 + sr)*K2 + k0 + sc];
            va0 = *(const uint4*)ah;       va1 = *(const uint4*)(ah + 4);
            vb0 = *(const uint4*)al;       vb1 = *(const uint4*)(al + 4);
        } else {
            const float* ap = g_h + (size_t)(m0 + sr)*K + 2*(k0 + sc);
            float4 f0 = *(const float4*)ap;
            float4 f1 = *(const float4*)(ap + 4);
            float4 f2 = *(const float4*)(ap + 8);
            float4 f3 = *(const float4*)(ap + 12);
            cvt2(f0.x, f0.y, hh[0], ll[0]); cvt2(f0.z, f0.w, hh[1], ll[1]);
            cvt2(f1.x, f1.y, hh[2], ll[2]); cvt2(f1.z, f1.w, hh[3], ll[3]);
            cvt2(f2.x, f2.y, hh[4], ll[4]); cvt2(f2.z, f2.w, hh[5], ll[5]);
            cvt2(f3.x, f3.y, hh[6], ll[6]); cvt2(f3.z, f3.w, hh[7], ll[7]);
        }
        const unsigned* wh = &WHp[(size_t)(n0 + sr)*K2 + k0 + sc];
        const unsigned* wl = &WLp[(size_t)(n0 + sr)*K2 + k0 + sc];
        uint4 vw0 = *(const uint4*)wh, vw1 = *(const uint4*)(wh + 4);
        uint4 vx0 = *(const uint4*)wl, vx1 = *(const uint4*)(wl + 4);

        __syncthreads();
        if (mode != 1) {
            *(uint4*)&sAH[sr][sc]     = va0; *(uint4*)&sAH[sr][sc + 4] = va1;
            *(uint4*)&sAL[sr][sc]     = vb0; *(uint4*)&sAL[sr][sc + 4] = vb1;
        } else {
            *(uint4*)&sAH[sr][sc]     = make_uint4(hh[0], hh[1], hh[2], hh[3]);
            *(uint4*)&sAH[sr][sc + 4] = make_uint4(hh[4], hh[5], hh[6], hh[7]);
            *(uint4*)&sAL[sr][sc]     = make_uint4(ll[0], ll[1], ll[2], ll[3]);
            *(uint4*)&sAL[sr][sc + 4] = make_uint4(ll[4], ll[5], ll[6], ll[7]);
        }
        *(uint4*)&sWH[sr][sc]     = vw0; *(uint4*)&sWH[sr][sc + 4] = vw1;
        *(uint4*)&sWL[sr][sc]     = vx0; *(uint4*)&sWL[sr][sc + 4] = vx1;
        __syncthreads();

#pragma unroll
        for (int ks = 0; ks < 2; ks++) {
            int kc = ks * 8;
            unsigned aH[2][4], aL[2][4];
#pragma unroll
            for (int mi = 0; mi < 2; mi++) {
                int r = wm + mi*16 + grp;
                aH[mi][0] = sAH[r][kc + qd];     aH[mi][1] = sAH[r + 8][kc + qd];
                aH[mi][2] = sAH[r][kc + qd + 4]; aH[mi][3] = sAH[r + 8][kc + qd + 4];
                aL[mi][0] = sAL[r][kc + qd];     aL[mi][1] = sAL[r + 8][kc + qd];
                aL[mi][2] = sAL[r][kc + qd + 4]; aL[mi][3] = sAL[r + 8][kc + qd + 4];
            }
#pragma unroll
            for (int ni = 0; ni < 8; ni++) {
                int cn = wn + ni*8 + grp;
                unsigned bh0 = sWH[cn][kc + qd], bh1 = sWH[cn][kc + qd + 4];
                unsigned bl0 = sWL[cn][kc + qd], bl1 = sWL[cn][kc + qd + 4];
#pragma unroll
                for (int mi = 0; mi < 2; mi++) {
                    mma_bf16(acc[mi][ni], aH[mi], bl0, bl1);
                    mma_bf16(acc[mi][ni], aL[mi], bh0, bh1);
                    mma_bf16(acc[mi][ni], aH[mi], bh0, bh1);
                }
            }
        }
    }

#pragma unroll
    for (int mi = 0; mi < 2; mi++)
#pragma unroll
        for (int ni = 0; ni < 8; ni++) {
            int r0 = m0 + wm + mi*16 + grp;
            int cb = n0 + wn + ni*8 + 2*qd;
            if (cb < N) {
                float bv0 = bias ? bias[cb] : 0.f;
                float bv1 = bias ? bias[cb + 1] : 0.f;
                float* d = acc[mi][ni];
                *(float2*)&C[(size_t)r0*N + cb]       = make_float2(d[0] + bv0, d[1] + bv1);
                *(float2*)&C[(size_t)(r0 + 8)*N + cb] = make_float2(d[2] + bv0, d[3] + bv1);
            }
        }
}

// ---------------- persistent step-loop kernel ----------------
// 148 blocks x 256 threads. Per step:
//   phase A (blocks 0..143): multi-job GEMM (gates 64, cg0 32, f1 16, f2 16, q 16)
//   grid sync
//   phase B (blocks 0..63, b=bid): attlogits+softmax+w@P+cell(i)+gather(i+1)
//   grid sync
__global__ void __launch_bounds__(256)
k_steps(const int* __restrict__ word_idx, const int* __restrict__ father_idx,
        const float* __restrict__ embed_tab, const float* __restrict__ W_alpha,
        const float* __restrict__ bias_H, const float* __restrict__ bias_I,
        const float* __restrict__ bias_f1, const float* __restrict__ bias_f2) {
    // GEMM staging
    __shared__ unsigned sAH[64][20], sAL[64][20], sWH[128][20], sWL[128][20];
    // phase-B scratch
    __shared__ float q_s[Ee];
    __shared__ float wa_s[Ee];
    __shared__ float alog[224];
    __shared__ float w_s[224];
    __shared__ float cg_s[Hh];
    __shared__ float red[8];
    __shared__ float sv;

    int bid = blockIdx.x;
    int tid = threadIdx.x;
    int warp = tid >> 5, lane = tid & 31;
    int grp = lane >> 2, qd = lane & 3;

    // GEMM job geometry (constant across steps)
    const float* A; int lda; const unsigned *WHp, *WLp; int ldw2; float* Cp; int N, ntile, local;
    bool gjob = (bid < 144);
    if (bid < 64)       { A = g_catX;  lda = 2048; WHp = cWHH;  WLp = cWHL;  ldw2 = 1024; N = 1024; ntile = 8; Cp = &g_gatesP[0][0]; local = bid; }
    else if (bid < 96)  { A = g_catX;  lda = 2048; WHp = cWIH;  WLp = cWIL;  ldw2 = 1024; N = 512;  ntile = 4; Cp = &g_cg0P[0][0];   local = bid - 64; }
    else if (bid < 112) { A = g_catF1; lda = 1024; WHp = cWF1H; WLp = cWF1L; ldw2 = 512;  N = 512;  ntile = 4; Cp = &g_f1P[0][0];    local = bid - 96; }
    else if (bid < 128) { A = g_catF2; lda = 1024; WHp = cWF2H; WLp = cWF2L; ldw2 = 512;  N = 512;  ntile = 4; Cp = &g_f2P[0][0];    local = bid - 112; }
    else                { A = g_hcat;  lda = 1024; WHp = cWQH;  WLp = cWQL;  ldw2 = 512;  N = 512;  ntile = 4; Cp = &g_qp[0][0];     local = bid - 128; }
    int tile = local % ntile, split = local / ntile;
    int n0 = tile * 128, k0f = split * 256;
    int wm = (warp & 1) * 32;
    int wn = (warp >> 1) * 32;
    int ar = tid >> 2, af = (tid & 3) * 8;
    int wr = tid >> 1, wc = (tid & 1) * 8;

    for (int i = 0; i < Tt; i++) {
        // ---- phase A: GEMM ----
        if (gjob) {
            float acc[2][4][4];
#pragma unroll
            for (int mi = 0; mi < 2; mi++)
#pragma unroll
                for (int ni = 0; ni < 4; ni++)
#pragma unroll
                    for (int r = 0; r < 4; r++) acc[mi][ni][r] = 0.f;

            for (int it = 0; it < 8; it++) {
                int kf = k0f + it*32;
                int ku = kf >> 1;
                const float* ap = A + (size_t)ar*lda + kf + af;
                float4 f0 = *(const float4*)ap;
                float4 f1 = *(const float4*)(ap + 4);
                unsigned h0,l0,h1,l1,h2,l2,h3,l3;
                cvt2(f0.x, f0.y, h0, l0); cvt2(f0.z, f0.w, h1, l1);
                cvt2(f1.x, f1.y, h2, l2); cvt2(f1.z, f1.w, h3, l3);
                const unsigned* wh = &WHp[(size_t)(n0 + wr)*ldw2 + ku + wc];
                const unsigned* wl = &WLp[(size_t)(n0 + wr)*ldw2 + ku + wc];
                uint4 vw0 = *(const uint4*)wh, vw1 = *(const uint4*)(wh + 4);
                uint4 vx0 = *(const uint4*)wl, vx1 = *(const uint4*)(wl + 4);

                __syncthreads();
                *(uint4*)&sAH[ar][(tid & 3)*4] = make_uint4(h0, h1, h2, h3);
                *(uint4*)&sAL[ar][(tid & 3)*4] = make_uint4(l0, l1, l2, l3);
                *(uint4*)&sWH[wr][wc]     = vw0; *(uint4*)&sWH[wr][wc + 4] = vw1;
                *(uint4*)&sWL[wr][wc]     = vx0; *(uint4*)&sWL[wr][wc + 4] = vx1;
                __syncthreads();

#pragma unroll
                for (int ks = 0; ks < 2; ks++) {
                    int kc = ks * 8;
                    unsigned aH[2][4], aL[2][4];
#pragma unroll
                    for (int mi = 0; mi < 2; mi++) {
                        int r = wm + mi*16 + grp;
                        aH[mi][0] = sAH[r][kc + qd];     aH[mi][1] = sAH[r + 8][kc + qd];
                        aH[mi][2] = sAH[r][kc + qd + 4]; aH[mi][3] = sAH[r + 8][kc + qd + 4];
                        aL[mi][0] = sAL[r][kc + qd];     aL[mi][1] = sAL[r + 8][kc + qd];
                        aL[mi][2] = sAL[r][kc + qd + 4]; aL[mi][3] = sAL[r + 8][kc + qd + 4];
                    }
#pragma unroll
                    for (int ni = 0; ni < 4; ni++) {
                        int cn = wn + ni*8 + grp;
                        unsigned bh0 = sWH[cn][kc + qd], bh1 = sWH[cn][kc + qd + 4];
                        unsigned bl0 = sWL[cn][kc + qd], bl1 = sWL[cn][kc + qd + 4];
#pragma unroll
                        for (int mi = 0; mi < 2; mi++) {
                            mma_bf16(acc[mi][ni], aH[mi], bl0, bl1);
                            mma_bf16(acc[mi][ni], aL[mi], bh0, bh1);
                            mma_bf16(acc[mi][ni], aH[mi], bh0, bh1);
                        }
                    }
                }
            }

            float* Cb = Cp + (size_t)split * 64 * N;
#pragma unroll
            for (int mi = 0; mi < 2; mi++)
#pragma unroll
                for (int ni = 0; ni < 4; ni++) {
                    int r0 = wm + mi*16 + grp;
                    int cb = n0 + wn + ni*8 + 2*qd;
                    float* d = acc[mi][ni];
                    *(float2*)&Cb[(size_t)r0*N + cb]       = make_float2(d[0], d[1]);
                    *(float2*)&Cb[(size_t)(r0 + 8)*N + cb] = make_float2(d[2], d[3]);
                }
        }
        grid_sync_();

        // ---- phase B: attention + cell + gather (blocks 0..63) ----
        if (bid < Bb) {
            int b = bid;
            if (i > 0) {
                // q = bq + sum qp partials; stage W_alpha
                for (int e = tid; e < Ee; e += 256) {
                    float s = g_bq[e];
#pragma unroll
                    for (int p = 0; p < 4; p++) s += g_qp[p][b*Ee + e];
                    q_s[e] = s;
                    wa_s[e] = W_alpha[e];
                }
                __syncthreads();
                // logits: warp per row
                for (int a = warp; a < ATT; a += 8) {
                    const float* pa = g_patt + ((size_t)(b*ATT) + a)*Ee;
                    float acc = 0.f;
#pragma unroll
                    for (int k = 0; k < 16; k++) {
                        int e = lane + 32*k;
                        acc += wa_s[e] * tanh_approx(q_s[e] + pa[e]);
                    }
#pragma unroll
                    for (int o = 16; o > 0; o >>= 1) acc += __shfl_down_sync(0xffffffffu, acc, o);
                    if (lane == 0) alog[a] = acc;
                }
                __syncthreads();
                // softmax over alog[0..195]
                float v = (tid < ATT) ? alog[tid] : -1e30f;
                float m = v;
#pragma unroll
                for (int o = 16; o > 0; o >>= 1) m = fmaxf(m, __shfl_xor_sync(0xffffffffu, m, o));
                if (lane == 0) red[warp] = m;
                __syncthreads();
                if (tid == 0) {
                    float mm = red[0];
                    for (int k = 1; k < 8; k++) mm = fmaxf(mm, red[k]);
                    sv = mm;
                }
                __syncthreads();
                float e = (tid < ATT) ? __expf(v - sv) : 0.f;
                float s = e;
#pragma unroll
                for (int o = 16; o > 0; o >>= 1) s += __shfl_xor_sync(0xffffffffu, s, o);
                __syncthreads();
                if (lane == 0) red[warp] = s;
                __syncthreads();
                if (tid == 0) {
                    float ss = 0.f;
                    for (int k = 0; k < 8; k++) ss += red[k];
                    sv = ss;
                }
                __syncthreads();
                if (tid < ATT) w_s[tid] = e / sv;
                __syncthreads();
                // w @ P
                int d0 = tid * 2;
                const float* base = g_pI + (size_t)b*ATT*Hh + d0;
                float ax = 0.f, ay = 0.f;
#pragma unroll 4
                for (int a = 0; a < ATT; a++) {
                    float2 v2 = *(const float2*)&base[(size_t)a*Hh];
                    float ww = w_s[a];
                    ax += ww * v2.x; ay += ww * v2.y;
                }
                cg_s[d0] = ax; cg_s[d0 + 1] = ay;
            } else {
                for (int d = tid; d < Hh; d += 256) cg_s[d] = g_cgatt[b*Hh + d];
            }
            __syncthreads();

            // cell(i)
            for (int d = tid; d < Hh; d += 256) {
                float gi = bias_H[d], go = bias_H[Hh + d];
#pragma unroll
                for (int p = 0; p < 8; p++) { gi += g_gatesP[p][b*1024 + d]; go += g_gatesP[p][b*1024 + 512 + d]; }
                float cg = bias_I[d] + cg_s[d];
#pragma unroll
                for (int p = 0; p < 8; p++) cg += g_cg0P[p][b*Hh + d];
                float f1 = bias_f1[d], f2 = bias_f2[d];
#pragma unroll
                for (int p = 0; p < 4; p++) { f1 += g_f1P[p][b*Hh + d]; f2 += g_f2P[p][b*Hh + d]; }
                gi = 1.f/(1.f + expf(-gi));
                go = 1.f/(1.f + expf(-go));
                cg = tanhf(cg);
                f1 = 1.f/(1.f + expf(-f1));
                f2 = 1.f/(1.f + expf(-f2));
                float nc = f1*g_ca[b*Hh + d] + f2*g_cf[b*Hh + d] + gi*cg;
                float nh = go * tanhf(nc);
                g_h[(b*Tt + i)*Hh + d] = nh;
                g_c[(b*Tt + i)*Hh + d] = nc;
            }
            __syncthreads();

            // gather(i+1)
            int ni = i + 1;
            if (ni < Tt) {
                int father = father_idx[b*Tt + ni];
                bool useF = (((ni - 1) % 3) != 0);
                int wa = word_idx[b*Tt + father];
                int wf = word_idx[b*Tt + ni - 1];
                for (int d = tid; d < Hh; d += 256) {
                    float xa = embed_tab[(size_t)wa*Ee + d];
                    float ha = g_h[(b*Tt + father)*Hh + d];
                    float ca = g_c[(b*Tt + father)*Hh + d];
                    float xf = 0.f, hf = 0.f, cf = 0.f;
                    if (useF) {
                        xf = embed_tab[(size_t)wf*Ee + d];
                        hf = g_h[(b*Tt + ni - 1)*Hh + d];
                        cf = g_c[(b*Tt + ni - 1)*Hh + d];
                    }
                    g_catX[b*2048 + d]        = xa;
                    g_catX[b*2048 + 512 + d]  = xf;
                    g_catX[b*2048 + 1024 + d] = ha;
                    g_catX[b*2048 + 1536 + d] = hf;
                    g_catF1[b*1024 + d]       = xa;
                    g_catF1[b*1024 + 512 + d] = ha;
                    g_catF2[b*1024 + d]       = xf;
                    g_catF2[b*1024 + 512 + d] = hf;
                    g_hcat[b*1024 + d]        = ha;
                    g_hcat[b*1024 + 512 + d]  = hf;
                    g_ca[b*Hh + d] = ca;
                    g_cf[b*Hh + d] = cf;
                }
            }
        }
        grid_sync_();
    }
}

// ---------------- fc_emb partials (init-only, fp32) ----------------
__global__ void __launch_bounds__(256)
k_gemm_fc(const float* __restrict__ A, const float* __restrict__ W) {
    int tile = blockIdx.x % 4, split = blockIdx.x / 4;
    int n0 = tile * 128, k0 = split * 256;
    __shared__ float As[16][64];
    __shared__ float Ws[16][132];
    int tid = threadIdx.x;
    int tx = tid & 15, ty = tid >> 4;
    int ar = tid >> 2, ak = (tid & 3) * 4;
    int wr = tid >> 1, wk = (tid & 1) * 8;
    const float* Ap = A + (size_t)ar*FCD + k0 + ak;
    const float* Wp = W + (size_t)(n0 + wr)*FCD + k0 + wk;
    float acc[4][8];
#pragma unroll
    for (int i = 0; i < 4; i++)
#pragma unroll
        for (int j = 0; j < 8; j++) acc[i][j] = 0.f;
    for (int kk = 0; kk < 256; kk += 16) {
        {
            float4 v = *(const float4*)&Ap[kk];
            As[ak+0][ar] = v.x; As[ak+1][ar] = v.y; As[ak+2][ar] = v.z; As[ak+3][ar] = v.w;
        }
        {
            float4 w0 = *(const float4*)&Wp[kk];
            float4 w1 = *(const float4*)&Wp[kk + 4];
            Ws[wk+0][wr] = w0.x; Ws[wk+1][wr] = w0.y; Ws[wk+2][wr] = w0.z; Ws[wk+3][wr] = w0.w;
            Ws[wk+4][wr] = w1.x; Ws[wk+5][wr] = w1.y; Ws[wk+6][wr] = w1.z; Ws[wk+7][wr] = w1.w;
        }
        __syncthreads();
#pragma unroll
        for (int k = 0; k < 16; k++) {
            float4 a  = *(const float4*)&As[k][ty*4];
            float4 w0 = *(const float4*)&Ws[k][tx*8];
            float4 w1 = *(const float4*)&Ws[k][tx*8 + 4];
            float av[4] = {a.x,a.y,a.z,a.w};
            float wv[8] = {w0.x,w0.y,w0.z,w0.w,w1.x,w1.y,w1.z,w1.w};
#pragma unroll
            for (int i = 0; i < 4; i++)
#pragma unroll
                for (int j = 0; j < 8; j++) acc[i][j] += av[i]*wv[j];
        }
        __syncthreads();
    }
    float* Cb = &g_fcp[0][0] + (size_t)split * 64 * Ee;
#pragma unroll
    for (int i = 0; i < 4; i++) {
        int m = ty*4 + i;
        *(float4*)&Cb[(size_t)m*Ee + n0 + tx*8]     = make_float4(acc[i][0],acc[i][1],acc[i][2],acc[i][3]);
        *(float4*)&Cb[(size_t)m*Ee + n0 + tx*8 + 4] = make_float4(acc[i][4],acc[i][5],acc[i][6],acc[i][7]);
    }
}

__global__ void k_gather0(const float* __restrict__ b_fc) {
    int b = blockIdx.x;
    for (int d = threadIdx.x; d < Hh; d += blockDim.x) {
        float s = b_fc[d];
#pragma unroll
        for (int p = 0; p < 8; p++) s += g_fcp[p][b*Ee + d];
        float xa = s;
        g_catX[b*2048 + d]        = xa;
        g_catX[b*2048 + 512 + d]  = 0.f;
        g_catX[b*2048 + 1024 + d] = 0.f;
        g_catX[b*2048 + 1536 + d] = 0.f;
        g_catF1[b*1024 + d]       = xa;
        g_catF1[b*1024 + 512 + d] = 0.f;
        g_catF2[b*1024 + d]       = 0.f;
        g_catF2[b*1024 + 512 + d] = 0.f;
        g_hcat[b*1024 + d]        = 0.f;
        g_hcat[b*1024 + 512 + d]  = 0.f;
        g_ca[b*Hh + d] = 0.f;
        g_cf[b*Hh + d] = 0.f;
    }
}

// 1-pass online log-softmax
__global__ void k_logsoftmax(float* __restrict__ out) {
    int r = blockIdx.x;
    float* row = out + (size_t)r*Vv;
    int tid = threadIdx.x;
    int wid = tid >> 5, lane = tid & 31;
    __shared__ float rm[8], rs[8];
    __shared__ float svM, svS;

    float m = -1e30f, s = 0.f;
    for (int j = tid; j < Vv; j += 256) {
        float v = row[j];
        if (v > m) { s = s*__expf(m - v) + 1.f; m = v; }
        else s += __expf(v - m);
    }
#pragma unroll
    for (int o = 16; o > 0; o >>= 1) {
        float mo = __shfl_xor_sync(0xffffffffu, m, o);
        float so = __shfl_xor_sync(0xffffffffu, s, o);
        float M = fmaxf(m, mo);
        s = s*__expf(m - M) + so*__expf(mo - M);
        m = M;
    }
    if (lane == 0) { rm[wid] = m; rs[wid] = s; }
    __syncthreads();
    if (tid == 0) {
        float M = rm[0], S = rs[0];
        for (int k = 1; k < 8; k++) {
            float M2 = fmaxf(M, rm[k]);
            S = S*__expf(M - M2) + rs[k]*__expf(rm[k] - M2);
            M = M2;
        }
        svM = M; svS = S;
    }
    __syncthreads();
    float lse = svM + logf(svS);
    for (int j = tid; j < Vv; j += 256) row[j] -= lse;
}

// ---------------- host ----------------
extern "C" void kernel_launch(void* const* d_in, const int* in_sizes, int n_in,
                              void* d_out, int out_size) {
    const int*   word_idx   = (const int*)d_in[0];
    const int*   father_idx = (const int*)d_in[1];
    const float* fc_feats   = (const float*)d_in[2];
    const float* att_feats  = (const float*)d_in[3];
    const float* W_fc       = (const float*)d_in[4];
    const float* b_fc       = (const float*)d_in[5];
    const float* W_att      = (const float*)d_in[6];
    const float* b_att      = (const float*)d_in[7];
    const float* embed_tab  = (const float*)d_in[8];
    const float* weight_f1  = (const float*)d_in[9];
    const float* bias_f1    = (const float*)d_in[10];
    const float* weight_f2  = (const float*)d_in[11];
    const float* bias_f2    = (const float*)d_in[12];
    const float* weight_H   = (const float*)d_in[13];
    const float* bias_H     = (const float*)d_in[14];
    const float* weight_I   = (const float*)d_in[15];
    const float* bias_I     = (const float*)d_in[16];
    const float* W_ha       = (const float*)d_in[17];
    const float* b_ha       = (const float*)d_in[18];
    const float* W_hf       = (const float*)d_in[19];
    const float* b_hf       = (const float*)d_in[20];
    const float* W_alpha    = (const float*)d_in[21];
    const float* b_alpha    = (const float*)d_in[22];
    const float* W_logit    = (const float*)d_in[23];
    const float* b_logit    = (const float*)d_in[24];
    float* out = (float*)d_out;
    (void)b_alpha; (void)n_in; (void)in_sizes; (void)out_size;

    // ---- one-time preprocessing ----
    k_zero_hc<<<512, 256>>>();
    k_build_wq<<<Ee, 256>>>(W_ha, b_ha, W_hf, b_hf);

    k_cvt<<<4096, 256>>>(0, att_feats, AF, Bb*ATT, AF, Bb*ATT);
    k_cvt<<<512, 256>>>(1, W_att, AF, Ee, AF, Ee);
    k_cvt<<<512, 256>>>(2, weight_I + 2048, 4096, Hh, 2048, Hh);
    k_cvt<<<1024, 256>>>(3, W_logit, Hh, Vv, Hh, VPAD);
    k_cvt<<<512, 256>>>(4, weight_H, 2048, 1024, 2048, 1024);
    k_cvt<<<512, 256>>>(5, weight_I, 4096, Hh, 2048, Hh);
    k_cvt<<<256, 256>>>(6, weight_f1, 1024, Hh, 1024, Hh);
    k_cvt<<<256, 256>>>(7, weight_f2, 1024, Hh, 1024, Hh);
    k_cvt<<<256, 256>>>(8, nullptr, 1024, Hh, 1024, Hh);

    k_gemm_fc<<<32, 256>>>(fc_feats, W_fc);

    {
        dim3 g(Ee/128, (Bb*ATT)/128);
        k_gemm_bigbf<<<g, 256>>>(0, b_att, nullptr, Bb*ATT, Ee, AF);
    }
    {
        dim3 g(Hh/128, (Bb*ATT)/128);
        k_gemm_bigbf<<<g, 256>>>(2, nullptr, nullptr, Bb*ATT, Hh, AF);
    }
    {
        dim3 g(Bb, 4);
        k_pmean<<<g, 128>>>();
    }
    k_gather0<<<Bb, 256>>>(b_fc);

    // ---- all 48 tree-LSTM steps in ONE persistent kernel ----
    k_steps<<<NBLK, 256>>>(word_idx, father_idx, embed_tab, W_alpha,
                           bias_H, bias_I, bias_f1, bias_f2);

    // logits + log_softmax
    {
        dim3 g((Vv + 127)/128, (Bb*Tt)/128);
        k_gemm_bigbf<<<g, 256>>>(1, b_logit, out, Bb*Tt, Vv, Hh);
    }
    k_logsoftmax<<<Bb*Tt, 256>>>(out);
}